// round 7
// baseline (speedup 1.0000x reference)
#include <cuda_runtime.h>
#include <cuda_fp16.h>

#define D_MODEL 768
#define N_HEADS 12
#define HEAD_DIM 64
#define BATCH 2
#define SEQ 4096
#define M_TOT 8192

// ---------------------------------------------------------------------------
// NO __device__ globals, NO address-taken locals (zero local memory).
// All scratch lives inside d_out (24 MiB), viewed as 8192 regions x 3072 B:
//   region r = bytes [r*3072, r*3072+3072)
//   [ +0,    +1536) : ATT row r, 768 fp16  (written by attn, read by proj)
//   [ +1536, +3072) : striped scratch pool (12 MiB total) for staged K/V fp16
// K/V staging (per wave = one batch, 12 heads):
//   chunk c = head*4096 + t  (c in 0..49151), 256 B each (K row 128B, V row 128B)
//   addr(c) = base + (c/6)*3072 + 1536 + (c%6)*256        (49152*256 = 12 MiB)
// ---------------------------------------------------------------------------

__device__ __forceinline__ unsigned pack2(float a, float b) {
    unsigned lo = (unsigned)__half_as_ushort(__float2half_rn(a));
    unsigned hi = (unsigned)__half_as_ushort(__float2half_rn(b));
    return lo | (hi << 16);
}
__device__ __forceinline__ float2 unpack2(unsigned v) {
    float2 r;
    r.x = __half2float(__ushort_as_half((unsigned short)(v & 0xFFFFu)));
    r.y = __half2float(__ushort_as_half((unsigned short)(v >> 16)));
    return r;
}

// ---------------------------------------------------------------------------
// Kernel A — K/V GEMM for one batch: K,V[h] = x_b @ W_attn[:, kv-slices] + bias.
// Grid (12 heads, 32 row-tiles), 256 threads. BM=128, BN=128 (K:0-63, V:64-127),
// BK=16, 8x8 per thread. Epilogue packs fp16 into striped scratch.
// ---------------------------------------------------------------------------
__global__ __launch_bounds__(256)
void kv_gemm_kernel(const float* __restrict__ x,
                    const float* __restrict__ W_attn,
                    const float* __restrict__ b_attn,
                    char* __restrict__ dbase, int b)
{
    __shared__ float As[16][128];
    __shared__ float Bs[16][128];

    const int h   = blockIdx.x;
    const int tid = threadIdx.x;
    const int tx = tid & 15, ty = tid >> 4;
    const int rowBase = blockIdx.y * 128;
    const float* A = x + (size_t)b * SEQ * D_MODEL;

    float acc[8][8];
#pragma unroll
    for (int i = 0; i < 8; i++)
#pragma unroll
        for (int j = 0; j < 8; j++) acc[i][j] = 0.f;

    for (int k0 = 0; k0 < D_MODEL; k0 += 16) {
#pragma unroll
        for (int i = 0; i < 2; i++) {
            int idx = tid + i * 256;
            int ar = idx >> 2, ac = (idx & 3) << 2;
            float4 v = *(const float4*)&A[(size_t)(rowBase + ar) * D_MODEL + k0 + ac];
            As[ac + 0][ar] = v.x; As[ac + 1][ar] = v.y;
            As[ac + 2][ar] = v.z; As[ac + 3][ar] = v.w;
        }
#pragma unroll
        for (int i = 0; i < 2; i++) {
            int idx = tid + i * 256;
            int br = idx >> 5, bc = (idx & 31) << 2;         // 0..124
            int gcol = (bc < 64) ? (768 + h * 64 + bc) : (1536 + h * 64 + bc - 64);
            float4 v = *(const float4*)&W_attn[(size_t)(k0 + br) * 2304 + gcol];
            Bs[br][bc] = v.x; Bs[br][bc + 1] = v.y;
            Bs[br][bc + 2] = v.z; Bs[br][bc + 3] = v.w;
        }
        __syncthreads();
#pragma unroll
        for (int kk = 0; kk < 16; kk++) {
            float4 a0 = *(const float4*)&As[kk][ty * 8];
            float4 a1 = *(const float4*)&As[kk][ty * 8 + 4];
            float4 b0 = *(const float4*)&Bs[kk][tx * 8];
            float4 b1 = *(const float4*)&Bs[kk][tx * 8 + 4];
#define AROW(I, AV) \
            acc[I][0]+=(AV)*b0.x; acc[I][1]+=(AV)*b0.y; acc[I][2]+=(AV)*b0.z; acc[I][3]+=(AV)*b0.w; \
            acc[I][4]+=(AV)*b1.x; acc[I][5]+=(AV)*b1.y; acc[I][6]+=(AV)*b1.z; acc[I][7]+=(AV)*b1.w;
            AROW(0, a0.x) AROW(1, a0.y) AROW(2, a0.z) AROW(3, a0.w)
            AROW(4, a1.x) AROW(5, a1.y) AROW(6, a1.z) AROW(7, a1.w)
#undef AROW
        }
        __syncthreads();
    }

    const int cb  = tx * 8;            // 0..120, never straddles 64
    const int isV = (cb >= 64);
    const int d0  = cb & 63;
    const int bbase = (isV ? 1536 : 768) + h * 64 + d0;
    float bv[8];
#pragma unroll
    for (int j = 0; j < 8; j++) bv[j] = b_attn[bbase + j];

#pragma unroll
    for (int i = 0; i < 8; i++) {
        int t = rowBase + ty * 8 + i;
        int c = h * SEQ + t;
        int p = c / 6, s = c - p * 6;
        char* pa = dbase + (size_t)p * 3072 + 1536 + s * 256 + isV * 128 + d0 * 2;
        uint4 w;
        w.x = pack2(acc[i][0] + bv[0], acc[i][1] + bv[1]);
        w.y = pack2(acc[i][2] + bv[2], acc[i][3] + bv[3]);
        w.z = pack2(acc[i][4] + bv[4], acc[i][5] + bv[5]);
        w.w = pack2(acc[i][6] + bv[6], acc[i][7] + bv[7]);
        *(uint4*)pa = w;
    }
}

// ---------------------------------------------------------------------------
// Kernel B — flash attention for one batch, Q generated on the fly.
// Grid (64 q-tiles, 12 heads), 128 threads. Thread = (q-row tid>>1, dim-half tid&1).
// Phase 1: Q[64x64] = x_rows @ Wq_h + bias, accumulated straight into qreg.
// Phase 2: flash over staged fp16 K/V tiles from the striped pool.
// Output: ATT fp16 into row-region front halves.
// ---------------------------------------------------------------------------
__global__ __launch_bounds__(128)
void attn_kernel(const float* __restrict__ x,
                 const float* __restrict__ W_attn,
                 const float* __restrict__ b_attn,
                 const int* __restrict__ attn_mask,
                 char* __restrict__ dbase, int b)
{
    const int qt = blockIdx.x, h = blockIdx.y;
    const int tid = threadIdx.x;
    const int row = tid >> 1, half = tid & 1;
    const int q_idx = qt * 64 + row;

    __shared__ float ks[64][68];     // stride 68: fp32, float4-aligned, low-conflict
    __shared__ float vs[64][68];
    __shared__ int   msk[64];

    // ---- Phase 1: Q-gen (ks aliased as x-tile, vs aliased as W-tile) ----
    float qreg[32];
#pragma unroll
    for (int d = 0; d < 32; d++) qreg[d] = 0.f;

    const float* xb = x + ((size_t)b * SEQ + qt * 64) * D_MODEL;
    for (int k0 = 0; k0 < D_MODEL; k0 += 16) {
        __syncthreads();
#pragma unroll
        for (int i = 0; i < 2; i++) {
            int idx = tid + i * 128;               // 0..255
            int r = idx >> 2, c4 = (idx & 3) << 2; // 64 rows x 16 cols
            float4 v = *(const float4*)&xb[(size_t)r * D_MODEL + k0 + c4];
            ks[r][c4] = v.x; ks[r][c4 + 1] = v.y; ks[r][c4 + 2] = v.z; ks[r][c4 + 3] = v.w;
        }
#pragma unroll
        for (int i = 0; i < 2; i++) {
            int idx = tid + i * 128;
            int kk = idx >> 4, c4 = (idx & 15) << 2;  // 16 rows x 64 cols
            float4 v = *(const float4*)&W_attn[(size_t)(k0 + kk) * 2304 + h * 64 + c4];
            vs[kk][c4] = v.x; vs[kk][c4 + 1] = v.y; vs[kk][c4 + 2] = v.z; vs[kk][c4 + 3] = v.w;
        }
        __syncthreads();
#pragma unroll
        for (int kk = 0; kk < 16; kk++) {
            float a = ks[row][kk];
#pragma unroll
            for (int d = 0; d < 32; d += 4) {
                float4 w = *(const float4*)&vs[kk][half * 32 + d];
                qreg[d]     += a * w.x;
                qreg[d + 1] += a * w.y;
                qreg[d + 2] += a * w.z;
                qreg[d + 3] += a * w.w;
            }
        }
    }
#pragma unroll
    for (int d = 0; d < 32; d++)
        qreg[d] = (qreg[d] + b_attn[h * 64 + half * 32 + d]) * 0.125f;  // fold 1/sqrt(64)

    // ---- Phase 2: flash over staged K/V ----
    float m = -1e30f, l = 0.f;
    float acc[32];
#pragma unroll
    for (int d = 0; d < 32; d++) acc[d] = 0.f;

    for (int kt = 0; kt <= qt; kt++) {
        __syncthreads();
        {
            int rr = tid >> 1, which = tid & 1;
            int c = h * SEQ + kt * 64 + rr;
            int p = c / 6, s = c - p * 6;
            const uint4* src =
                (const uint4*)(dbase + (size_t)p * 3072 + 1536 + s * 256 + which * 128);
            float (*dst)[68] = which ? vs : ks;
#pragma unroll
            for (int w8 = 0; w8 < 8; w8++) {
                uint4 u = src[w8];
                float2 f0 = unpack2(u.x), f1 = unpack2(u.y);
                float2 f2 = unpack2(u.z), f3 = unpack2(u.w);
                dst[rr][w8 * 8 + 0] = f0.x; dst[rr][w8 * 8 + 1] = f0.y;
                dst[rr][w8 * 8 + 2] = f1.x; dst[rr][w8 * 8 + 3] = f1.y;
                dst[rr][w8 * 8 + 4] = f2.x; dst[rr][w8 * 8 + 5] = f2.y;
                dst[rr][w8 * 8 + 6] = f3.x; dst[rr][w8 * 8 + 7] = f3.y;
            }
        }
        if (tid < 64) msk[tid] = attn_mask[b * SEQ + kt * 64 + tid];
        __syncthreads();

        for (int j = 0; j < 64; j++) {
            const int kj = kt * 64 + j;
            float partial = 0.f;
#pragma unroll
            for (int d = 0; d < 32; d += 4) {
                float4 kv = *(const float4*)&ks[j][half * 32 + d];
                partial += qreg[d]     * kv.x;
                partial += qreg[d + 1] * kv.y;
                partial += qreg[d + 2] * kv.z;
                partial += qreg[d + 3] * kv.w;
            }
            float s = partial + __shfl_xor_sync(0xffffffffu, partial, 1);
            const bool masked = (kj > q_idx) || (msk[j] == 0);
            if (masked) s = -1e30f;   // exp underflows to 0, matching ref's -10000

            float mnew = fmaxf(m, s);
            if (mnew > m) {
                float corr = __expf(m - mnew);
                l *= corr;
#pragma unroll
                for (int d = 0; d < 32; d++) acc[d] *= corr;
                m = mnew;
            }
            float p = __expf(s - m);
            l += p;
#pragma unroll
            for (int d = 0; d < 32; d += 4) {
                float4 vv = *(const float4*)&vs[j][half * 32 + d];
                acc[d]     += p * vv.x;
                acc[d + 1] += p * vv.y;
                acc[d + 2] += p * vv.z;
                acc[d + 3] += p * vv.w;
            }
        }
    }

    const float inv = 1.f / l;
    char* op = dbase + (size_t)(b * SEQ + q_idx) * 3072 + (size_t)(h * 64 + half * 32) * 2;
#pragma unroll
    for (int i = 0; i < 4; i++) {
        uint4 w;
        w.x = pack2(acc[i * 8 + 0] * inv, acc[i * 8 + 1] * inv);
        w.y = pack2(acc[i * 8 + 2] * inv, acc[i * 8 + 3] * inv);
        w.z = pack2(acc[i * 8 + 4] * inv, acc[i * 8 + 5] * inv);
        w.w = pack2(acc[i * 8 + 6] * inv, acc[i * 8 + 7] * inv);
        ((uint4*)op)[i] = w;
    }
}

// ---------------------------------------------------------------------------
// Kernel C — proj GEMM: out[8192,768] = ATT(fp16, striped) @ W_proj + bias.
// BM=32, BN=768 (one block owns a full 32-row stripe -> epilogue overwrite of
// the striped ATT bytes is hazard-free), BK=8, 256 threads (32 rows x 8 groups),
// 96 outputs/thread as 24 float4.
// ---------------------------------------------------------------------------
__global__ __launch_bounds__(256)
void proj_kernel(const char* __restrict__ att_base,
                 const float* __restrict__ W_proj,
                 const float* __restrict__ b_proj,
                 float* __restrict__ out)
{
    __shared__ float As[32][8];
    __shared__ float Bs[8][768];

    const int tid = threadIdx.x;
    const int r = tid >> 3, g = tid & 7;
    const int rowBase = blockIdx.x * 32;

    float4 acc[24];
#pragma unroll
    for (int j = 0; j < 24; j++) acc[j] = make_float4(0.f, 0.f, 0.f, 0.f);

    for (int k0 = 0; k0 < D_MODEL; k0 += 8) {
        __syncthreads();
        if (tid < 32) {
            uint4 u = *(const uint4*)(att_base + (size_t)(rowBase + tid) * 3072
                                      + (size_t)k0 * 2);
            float2 f0 = unpack2(u.x), f1 = unpack2(u.y);
            float2 f2 = unpack2(u.z), f3 = unpack2(u.w);
            As[tid][0] = f0.x; As[tid][1] = f0.y; As[tid][2] = f1.x; As[tid][3] = f1.y;
            As[tid][4] = f2.x; As[tid][5] = f2.y; As[tid][6] = f3.x; As[tid][7] = f3.y;
        }
#pragma unroll
        for (int i = 0; i < 6; i++) {
            int idx = tid + i * 256;                 // 0..1535 float4 slots
            int kb = idx / 192, c4 = (idx - kb * 192) << 2;
            float4 v = *(const float4*)&W_proj[(size_t)(k0 + kb) * D_MODEL + c4];
            Bs[kb][c4] = v.x; Bs[kb][c4 + 1] = v.y;
            Bs[kb][c4 + 2] = v.z; Bs[kb][c4 + 3] = v.w;
        }
        __syncthreads();
#pragma unroll
        for (int k = 0; k < 8; k++) {
            float a = As[r][k];
#pragma unroll
            for (int j = 0; j < 24; j++) {
                float4 bb = *(const float4*)&Bs[k][g * 4 + j * 32];
                acc[j].x += a * bb.x; acc[j].y += a * bb.y;
                acc[j].z += a * bb.z; acc[j].w += a * bb.w;
            }
        }
    }
    __syncthreads();   // all striped-ATT reads complete before the overwrite below
#pragma unroll
    for (int j = 0; j < 24; j++) {
        int cofs = g * 4 + j * 32;
        float4 bv = *(const float4*)&b_proj[cofs];
        float4 o;
        o.x = acc[j].x + bv.x; o.y = acc[j].y + bv.y;
        o.z = acc[j].z + bv.z; o.w = acc[j].w + bv.w;
        *(float4*)&out[(size_t)(rowBase + r) * D_MODEL + cofs] = o;
    }
}

// ---------------------------------------------------------------------------
extern "C" void kernel_launch(void* const* d_in, const int* in_sizes, int n_in,
                              void* d_out, int out_size)
{
    const float* x      = (const float*)d_in[0];  // [2,4096,768]
    const int*   amask  = (const int*)d_in[1];    // [2,4096]
    const float* W_attn = (const float*)d_in[2];  // [768,2304]
    const float* b_attn = (const float*)d_in[3];  // [2304]
    const float* W_proj = (const float*)d_in[4];  // [768,768]
    const float* b_proj = (const float*)d_in[5];  // [768]
    float*       out    = (float*)d_out;          // [2,4096,768]
    char*        dbase  = (char*)d_out;

    for (int b = 0; b < BATCH; b++) {
        kv_gemm_kernel<<<dim3(N_HEADS, SEQ / 128), 256>>>(x, W_attn, b_attn, dbase, b);
        attn_kernel<<<dim3(SEQ / 64, N_HEADS), 128>>>(x, W_attn, b_attn, amask, dbase, b);
    }
    proj_kernel<<<M_TOT / 32, 256>>>(dbase, W_proj, b_proj, out);
}

// round 8
// speedup vs baseline: 4.0755x; 4.0755x over previous
#include <cuda_runtime.h>
#include <cuda_fp16.h>
#include <cstdint>

#define D_MODEL 768
#define N_HEADS 12
#define BATCH 2
#define SEQ 4096
#define M_TOT 8192
// 1/sqrt(64) * log2(e) folded into Q at GEMM time (softmax done in base-2)
#define QSCALE 0.1803368801f

// ---------------------------------------------------------------------------
// Scratch lives inside d_out (24 MiB), 8192 regions x 3072 B:
//   [ +0,    +1536) : Q fp16 (written by qkv gemm) then ATT fp16 (overwritten
//                     in-place by attn for its own rows/head slice only)
//   [ +1536, +3072) : striped K/V pool (one batch), chunk c = h*4096+t:
//                     addr = (c/6)*3072 + 1536 + (c%6)*256  (K 128B | V 128B)
// ---------------------------------------------------------------------------

__device__ __forceinline__ unsigned packh2(float a, float b) {
    unsigned lo = (unsigned)__half_as_ushort(__float2half_rn(a));
    unsigned hi = (unsigned)__half_as_ushort(__float2half_rn(b));
    return lo | (hi << 16);
}
__device__ __forceinline__ float2 unpack2(unsigned v) {
    float2 r;
    r.x = __half2float(__ushort_as_half((unsigned short)(v & 0xFFFFu)));
    r.y = __half2float(__ushort_as_half((unsigned short)(v >> 16)));
    return r;
}
__device__ __forceinline__ float ex2(float x) {
    float y; asm("ex2.approx.f32 %0, %1;" : "=f"(y) : "f"(x)); return y;
}
__device__ __forceinline__ void mma16816(float* d, const uint32_t* a,
                                         const uint32_t* b) {
    asm volatile(
        "mma.sync.aligned.m16n8k16.row.col.f32.f16.f16.f32 "
        "{%0,%1,%2,%3}, {%4,%5,%6,%7}, {%8,%9}, {%0,%1,%2,%3};"
        : "+f"(d[0]), "+f"(d[1]), "+f"(d[2]), "+f"(d[3])
        : "r"(a[0]), "r"(a[1]), "r"(a[2]), "r"(a[3]), "r"(b[0]), "r"(b[1]));
}

// ---------------------------------------------------------------------------
// Kernel 1 — QKV GEMM for one batch: [4096,768] @ [768,2304] + bias.
// BM=128,BN=128,BK=16, 256 thr, 8x8/thread. Epilogue: Q*(QSCALE) fp16 -> ATT
// front halves; K,V fp16 -> striped pool.
// ---------------------------------------------------------------------------
__global__ __launch_bounds__(256)
void qkv_gemm_kernel(const float* __restrict__ x,
                     const float* __restrict__ W_attn,
                     const float* __restrict__ b_attn,
                     char* __restrict__ dbase, int b)
{
    __shared__ float As[16][128];
    __shared__ float Bs[16][128];

    const int tid = threadIdx.x;
    const int tx = tid & 15, ty = tid >> 4;
    const int rowBase = blockIdx.y * 128;
    const int colBase = blockIdx.x * 128;
    const float* A = x + (size_t)b * SEQ * D_MODEL;

    float acc[8][8];
#pragma unroll
    for (int i = 0; i < 8; i++)
#pragma unroll
        for (int j = 0; j < 8; j++) acc[i][j] = 0.f;

    for (int k0 = 0; k0 < D_MODEL; k0 += 16) {
#pragma unroll
        for (int i = 0; i < 2; i++) {
            int idx = tid + i * 256;
            int ar = idx >> 2, ac = (idx & 3) << 2;
            float4 v = *(const float4*)&A[(size_t)(rowBase + ar) * D_MODEL + k0 + ac];
            As[ac + 0][ar] = v.x; As[ac + 1][ar] = v.y;
            As[ac + 2][ar] = v.z; As[ac + 3][ar] = v.w;
        }
#pragma unroll
        for (int i = 0; i < 2; i++) {
            int idx = tid + i * 256;
            int br = idx >> 5, bc = (idx & 31) << 2;
            float4 v = *(const float4*)&W_attn[(size_t)(k0 + br) * 2304 + colBase + bc];
            Bs[br][bc] = v.x; Bs[br][bc + 1] = v.y;
            Bs[br][bc + 2] = v.z; Bs[br][bc + 3] = v.w;
        }
        __syncthreads();
#pragma unroll
        for (int kk = 0; kk < 16; kk++) {
            float4 a0 = *(const float4*)&As[kk][ty * 8];
            float4 a1 = *(const float4*)&As[kk][ty * 8 + 4];
            float4 b0 = *(const float4*)&Bs[kk][tx * 8];
            float4 b1 = *(const float4*)&Bs[kk][tx * 8 + 4];
#define AROW(I, AV) \
            acc[I][0]+=(AV)*b0.x; acc[I][1]+=(AV)*b0.y; acc[I][2]+=(AV)*b0.z; acc[I][3]+=(AV)*b0.w; \
            acc[I][4]+=(AV)*b1.x; acc[I][5]+=(AV)*b1.y; acc[I][6]+=(AV)*b1.z; acc[I][7]+=(AV)*b1.w;
            AROW(0, a0.x) AROW(1, a0.y) AROW(2, a0.z) AROW(3, a0.w)
            AROW(4, a1.x) AROW(5, a1.y) AROW(6, a1.z) AROW(7, a1.w)
#undef AROW
        }
        __syncthreads();
    }

    const int cb    = colBase + tx * 8;     // multiple of 8; never straddles 64/768
    const int which = cb / 768;             // 0=Q 1=K 2=V
    const int cc    = cb - which * 768;
    const int h     = cc >> 6;
    const int d0    = cc & 63;
    float bv[8];
#pragma unroll
    for (int j = 0; j < 8; j++) bv[j] = b_attn[cb + j];

#pragma unroll
    for (int i = 0; i < 8; i++) {
        int t = rowBase + ty * 8 + i;
        char* pa;
        float sc;
        if (which == 0) {
            pa = dbase + (size_t)(b * SEQ + t) * 3072 + (size_t)(h * 64 + d0) * 2;
            sc = QSCALE;
        } else {
            int c = h * SEQ + t;
            int p = c / 6, s = c - p * 6;
            pa = dbase + (size_t)p * 3072 + 1536 + s * 256 + (which == 2 ? 128 : 0) + d0 * 2;
            sc = 1.f;
        }
        uint4 w;
        w.x = packh2((acc[i][0] + bv[0]) * sc, (acc[i][1] + bv[1]) * sc);
        w.y = packh2((acc[i][2] + bv[2]) * sc, (acc[i][3] + bv[3]) * sc);
        w.z = packh2((acc[i][4] + bv[4]) * sc, (acc[i][5] + bv[5]) * sc);
        w.w = packh2((acc[i][6] + bv[6]) * sc, (acc[i][7] + bv[7]) * sc);
        *(uint4*)pa = w;
    }
}

// ---------------------------------------------------------------------------
// Kernel 2 — tensor-core flash attention for one batch.
// Grid (64 qt, 12 h), 128 threads (4 warps). Warp w: q-rows w*16..w*16+15.
// S = Q K^T via mma.m16n8k16 (Q fp16 from ATT slots, K fp16 from pool),
// softmax in C-fragment layout (base-2), P repacked in registers to A-frags,
// O += P V via mma with V staged transposed+swizzled. Output fp16 in-place.
// ---------------------------------------------------------------------------
__global__ __launch_bounds__(128)
void attn_mma_kernel(const int* __restrict__ attn_mask,
                     char* __restrict__ dbase, int b)
{
    const int qt   = (int)gridDim.x - 1 - (int)blockIdx.x;  // heavy tiles first
    const int h    = blockIdx.y;
    const int tid  = threadIdx.x;
    const int warp = tid >> 5, lane = tid & 31;
    const int lr   = lane >> 2;          // 0..7
    const int koff = (lane & 3) * 2;     // 0,2,4,6

    __shared__ __half Qs[64][72];
    __shared__ __half Ks[64][72];
    __shared__ __half Vt[64][72];        // [dim][swizzled key]
    __shared__ int    msk[64];

    // ---- stage Q tile (once) ----
#pragma unroll
    for (int i = 0; i < 4; i++) {
        int idx = tid + i * 128;         // 512 slots of 8 halves
        int rr = idx >> 3, c8 = (idx & 7) * 8;
        const char* src = dbase + (size_t)(b * SEQ + qt * 64 + rr) * 3072
                        + (size_t)(h * 64 + c8) * 2;
        *(uint4*)&Qs[rr][c8] = *(const uint4*)src;
    }
    __syncthreads();

    // A-fragments of Q (warp rows warp*16 .. +15)
    uint32_t qa[4][4];
    const int qr = warp * 16 + lr;
#pragma unroll
    for (int ks = 0; ks < 4; ks++) {
        qa[ks][0] = *(const uint32_t*)&Qs[qr][ks * 16 + koff];
        qa[ks][1] = *(const uint32_t*)&Qs[qr + 8][ks * 16 + koff];
        qa[ks][2] = *(const uint32_t*)&Qs[qr][ks * 16 + koff + 8];
        qa[ks][3] = *(const uint32_t*)&Qs[qr + 8][ks * 16 + koff + 8];
    }

    const int q0 = qt * 64 + qr;         // global q row (within batch)
    const int q1 = q0 + 8;

    float m0 = -1e30f, m1 = -1e30f, l0 = 0.f, l1 = 0.f;
    float O[8][4];
#pragma unroll
    for (int nb = 0; nb < 8; nb++)
#pragma unroll
        for (int j = 0; j < 4; j++) O[nb][j] = 0.f;

    for (int kt = 0; kt <= qt; kt++) {
        __syncthreads();
        // ---- stage K (raw fp16 copy) and V (transposed + swizzled) ----
#pragma unroll
        for (int i = 0; i < 4; i++) {
            int idx = tid + i * 128;
            int rr = idx >> 3, c8 = (idx & 7) * 8;
            int c = h * SEQ + kt * 64 + rr;
            int p = c / 6, s = c - p * 6;
            const char* base = dbase + (size_t)p * 3072 + 1536 + s * 256;
            *(uint4*)&Ks[rr][c8] = *(const uint4*)(base + c8 * 2);
            uint4 vv = *(const uint4*)(base + 128 + c8 * 2);
            int vcol = (rr + c8) & 63;   // swizzle: col = (key + 8*(dim>>3)) & 63
            Vt[c8 + 0][vcol] = __ushort_as_half((unsigned short)(vv.x & 0xFFFFu));
            Vt[c8 + 1][vcol] = __ushort_as_half((unsigned short)(vv.x >> 16));
            Vt[c8 + 2][vcol] = __ushort_as_half((unsigned short)(vv.y & 0xFFFFu));
            Vt[c8 + 3][vcol] = __ushort_as_half((unsigned short)(vv.y >> 16));
            Vt[c8 + 4][vcol] = __ushort_as_half((unsigned short)(vv.z & 0xFFFFu));
            Vt[c8 + 5][vcol] = __ushort_as_half((unsigned short)(vv.z >> 16));
            Vt[c8 + 6][vcol] = __ushort_as_half((unsigned short)(vv.w & 0xFFFFu));
            Vt[c8 + 7][vcol] = __ushort_as_half((unsigned short)(vv.w >> 16));
        }
        if (tid < 64) msk[tid] = attn_mask[b * SEQ + kt * 64 + tid];
        __syncthreads();

        // ---- S = Q K^T ----
        float S[8][4];
#pragma unroll
        for (int nb = 0; nb < 8; nb++)
#pragma unroll
            for (int j = 0; j < 4; j++) S[nb][j] = 0.f;
#pragma unroll
        for (int ks = 0; ks < 4; ks++) {
#pragma unroll
            for (int nb = 0; nb < 8; nb++) {
                uint32_t kb[2];
                kb[0] = *(const uint32_t*)&Ks[nb * 8 + lr][ks * 16 + koff];
                kb[1] = *(const uint32_t*)&Ks[nb * 8 + lr][ks * 16 + koff + 8];
                mma16816(S[nb], qa[ks], kb);
            }
        }

        // ---- mask + online softmax (scores already scaled by log2e/8) ----
        const bool diag = (kt == qt);
        float mx0 = -1e30f, mx1 = -1e30f;
#pragma unroll
        for (int nb = 0; nb < 8; nb++) {
            int cc = nb * 8 + koff;
            int kj = kt * 64 + cc;
            bool ok0 = msk[cc] != 0, ok1 = msk[cc + 1] != 0;
            bool a00 = ok0 && (!diag || kj     <= q0);
            bool a01 = ok1 && (!diag || kj + 1 <= q0);
            bool a10 = ok0 && (!diag || kj     <= q1);
            bool a11 = ok1 && (!diag || kj + 1 <= q1);
            S[nb][0] = a00 ? S[nb][0] : -1e30f;
            S[nb][1] = a01 ? S[nb][1] : -1e30f;
            S[nb][2] = a10 ? S[nb][2] : -1e30f;
            S[nb][3] = a11 ? S[nb][3] : -1e30f;
            mx0 = fmaxf(mx0, fmaxf(S[nb][0], S[nb][1]));
            mx1 = fmaxf(mx1, fmaxf(S[nb][2], S[nb][3]));
        }
        mx0 = fmaxf(mx0, __shfl_xor_sync(0xffffffffu, mx0, 1));
        mx0 = fmaxf(mx0, __shfl_xor_sync(0xffffffffu, mx0, 2));
        mx1 = fmaxf(mx1, __shfl_xor_sync(0xffffffffu, mx1, 1));
        mx1 = fmaxf(mx1, __shfl_xor_sync(0xffffffffu, mx1, 2));
        float m0n = fmaxf(m0, mx0), m1n = fmaxf(m1, mx1);
        float corr0 = ex2(m0 - m0n), corr1 = ex2(m1 - m1n);
        m0 = m0n; m1 = m1n;

        uint32_t pa[4][4];
        float sum0 = 0.f, sum1 = 0.f;
#pragma unroll
        for (int nb = 0; nb < 8; nb++) {
            float p00 = ex2(S[nb][0] - m0), p01 = ex2(S[nb][1] - m0);
            float p10 = ex2(S[nb][2] - m1), p11 = ex2(S[nb][3] - m1);
            sum0 += p00 + p01; sum1 += p10 + p11;
            int ksv = nb >> 1, hi = (nb & 1) * 2;
            pa[ksv][hi + 0] = packh2(p00, p01);
            pa[ksv][hi + 1] = packh2(p10, p11);
        }
        l0 = l0 * corr0 + sum0;
        l1 = l1 * corr1 + sum1;
#pragma unroll
        for (int nb = 0; nb < 8; nb++) {
            O[nb][0] *= corr0; O[nb][1] *= corr0;
            O[nb][2] *= corr1; O[nb][3] *= corr1;
        }
        // fix fragment index order: pa[ksv] = {r0(nb=2k), r1(nb=2k), r0(nb=2k+1), r1(nb=2k+1)}
        // matches A-frag {a0,a1,a2,a3} = {(r,k_lo),(r+8,k_lo),(r,k_hi),(r+8,k_hi)}

        // ---- O += P V ----
#pragma unroll
        for (int ksv = 0; ksv < 4; ksv++) {
#pragma unroll
            for (int nb = 0; nb < 8; nb++) {
                uint32_t vb[2];
                int k0c = ksv * 16 + koff;
                vb[0] = *(const uint32_t*)&Vt[nb * 8 + lr][(k0c + 8 * nb) & 63];
                vb[1] = *(const uint32_t*)&Vt[nb * 8 + lr][(k0c + 8 + 8 * nb) & 63];
                mma16816(O[nb], pa[ksv], vb);
            }
        }
    }

    // ---- epilogue ----
    l0 += __shfl_xor_sync(0xffffffffu, l0, 1);
    l0 += __shfl_xor_sync(0xffffffffu, l0, 2);
    l1 += __shfl_xor_sync(0xffffffffu, l1, 1);
    l1 += __shfl_xor_sync(0xffffffffu, l1, 2);
    float inv0 = 1.f / l0, inv1 = 1.f / l1;

    char* r0p = dbase + (size_t)(b * SEQ + q0) * 3072 + (size_t)(h * 64 + koff) * 2;
    char* r1p = dbase + (size_t)(b * SEQ + q1) * 3072 + (size_t)(h * 64 + koff) * 2;
#pragma unroll
    for (int nb = 0; nb < 8; nb++) {
        *(uint32_t*)(r0p + nb * 16) = packh2(O[nb][0] * inv0, O[nb][1] * inv0);
        *(uint32_t*)(r1p + nb * 16) = packh2(O[nb][2] * inv1, O[nb][3] * inv1);
    }
}

// ---------------------------------------------------------------------------
// Kernel 3 — proj GEMM: out[8192,768] = ATT(fp16 rows in-place) @ W_proj + b.
// BM=32, BN=768 (block owns full row stripe -> in-place overwrite safe), BK=8.
// ---------------------------------------------------------------------------
__global__ __launch_bounds__(256)
void proj_kernel(const char* __restrict__ att_base,
                 const float* __restrict__ W_proj,
                 const float* __restrict__ b_proj,
                 float* __restrict__ out)
{
    __shared__ float As[32][8];
    __shared__ float Bs[8][768];

    const int tid = threadIdx.x;
    const int r = tid >> 3, g = tid & 7;
    const int rowBase = blockIdx.x * 32;

    float4 acc[24];
#pragma unroll
    for (int j = 0; j < 24; j++) acc[j] = make_float4(0.f, 0.f, 0.f, 0.f);

    for (int k0 = 0; k0 < D_MODEL; k0 += 8) {
        __syncthreads();
        if (tid < 32) {
            uint4 u = *(const uint4*)(att_base + (size_t)(rowBase + tid) * 3072
                                      + (size_t)k0 * 2);
            float2 f0 = unpack2(u.x), f1 = unpack2(u.y);
            float2 f2 = unpack2(u.z), f3 = unpack2(u.w);
            As[tid][0] = f0.x; As[tid][1] = f0.y; As[tid][2] = f1.x; As[tid][3] = f1.y;
            As[tid][4] = f2.x; As[tid][5] = f2.y; As[tid][6] = f3.x; As[tid][7] = f3.y;
        }
#pragma unroll
        for (int i = 0; i < 6; i++) {
            int idx = tid + i * 256;
            int kb = idx / 192, c4 = (idx - kb * 192) << 2;
            float4 v = *(const float4*)&W_proj[(size_t)(k0 + kb) * D_MODEL + c4];
            Bs[kb][c4] = v.x; Bs[kb][c4 + 1] = v.y;
            Bs[kb][c4 + 2] = v.z; Bs[kb][c4 + 3] = v.w;
        }
        __syncthreads();
#pragma unroll
        for (int k = 0; k < 8; k++) {
            float a = As[r][k];
#pragma unroll
            for (int j = 0; j < 24; j++) {
                float4 bb = *(const float4*)&Bs[k][g * 4 + j * 32];
                acc[j].x += a * bb.x; acc[j].y += a * bb.y;
                acc[j].z += a * bb.z; acc[j].w += a * bb.w;
            }
        }
    }
    __syncthreads();
#pragma unroll
    for (int j = 0; j < 24; j++) {
        int cofs = g * 4 + j * 32;
        float4 bv = *(const float4*)&b_proj[cofs];
        float4 o;
        o.x = acc[j].x + bv.x; o.y = acc[j].y + bv.y;
        o.z = acc[j].z + bv.z; o.w = acc[j].w + bv.w;
        *(float4*)&out[(size_t)(rowBase + r) * D_MODEL + cofs] = o;
    }
}

// ---------------------------------------------------------------------------
extern "C" void kernel_launch(void* const* d_in, const int* in_sizes, int n_in,
                              void* d_out, int out_size)
{
    const float* x      = (const float*)d_in[0];
    const int*   amask  = (const int*)d_in[1];
    const float* W_attn = (const float*)d_in[2];
    const float* b_attn = (const float*)d_in[3];
    const float* W_proj = (const float*)d_in[4];
    const float* b_proj = (const float*)d_in[5];
    float*       out    = (float*)d_out;
    char*        dbase  = (char*)d_out;

    for (int b = 0; b < BATCH; b++) {
        qkv_gemm_kernel<<<dim3(2304 / 128, SEQ / 128), 256>>>(x, W_attn, b_attn, dbase, b);
        attn_mma_kernel<<<dim3(SEQ / 64, N_HEADS), 128>>>(amask, dbase, b);
    }
    proj_kernel<<<M_TOT / 32, 256>>>(dbase, W_proj, b_proj, out);
}

// round 9
// speedup vs baseline: 4.9192x; 1.2070x over previous
#include <cuda_runtime.h>
#include <cuda_fp16.h>
#include <cstdint>

#define D_MODEL 768
#define N_HEADS 12
#define BATCH 2
#define SEQ 4096
#define M_TOT 8192
// 1/sqrt(64) * log2(e) folded into Q at GEMM time (softmax done in base-2)
#define QSCALE 0.1803368801f

// ---------------------------------------------------------------------------
// Scratch lives inside d_out (24 MiB), 8192 regions x 3072 B:
//   [ +0,    +1536) : Q fp16 (written by qkv gemm) then ATT fp16 (overwritten
//                     in-place by attn for its own rows/head slice only)
//   [ +1536, +3072) : striped K/V pool (one batch), chunk c = h*4096+t:
//                     addr = (c/6)*3072 + 1536 + (c%6)*256  (K 128B | V 128B)
// ---------------------------------------------------------------------------

__device__ __forceinline__ unsigned packh2(float a, float b) {
    unsigned lo = (unsigned)__half_as_ushort(__float2half_rn(a));
    unsigned hi = (unsigned)__half_as_ushort(__float2half_rn(b));
    return lo | (hi << 16);
}
__device__ __forceinline__ float2 unpack2(unsigned v) {
    float2 r;
    r.x = __half2float(__ushort_as_half((unsigned short)(v & 0xFFFFu)));
    r.y = __half2float(__ushort_as_half((unsigned short)(v >> 16)));
    return r;
}
__device__ __forceinline__ float ex2(float x) {
    float y; asm("ex2.approx.f32 %0, %1;" : "=f"(y) : "f"(x)); return y;
}
__device__ __forceinline__ void mma16816(float* d, const uint32_t* a,
                                         const uint32_t* b) {
    asm volatile(
        "mma.sync.aligned.m16n8k16.row.col.f32.f16.f16.f32 "
        "{%0,%1,%2,%3}, {%4,%5,%6,%7}, {%8,%9}, {%0,%1,%2,%3};"
        : "+f"(d[0]), "+f"(d[1]), "+f"(d[2]), "+f"(d[3])
        : "r"(a[0]), "r"(a[1]), "r"(a[2]), "r"(a[3]), "r"(b[0]), "r"(b[1]));
}

// ---------------------------------------------------------------------------
// Kernel 1 — HMMA QKV GEMM for one batch: [4096,768] @ [768,2304] + bias.
// BM=128, BN=128, BK=32, 256 threads = 8 warps (4 m x 2 n), warp tile 32x64.
// fp32 gmem tiles converted to fp16 in smem; W stored transposed [n][k] so
// B-fragments are direct u32 LDS (same convention as the attn kernel's K).
// Epilogue: Q*(QSCALE) fp16 -> region front halves; K,V fp16 -> striped pool.
// ---------------------------------------------------------------------------
__global__ __launch_bounds__(256)
void qkv_hmma_kernel(const float* __restrict__ x,
                     const float* __restrict__ W_attn,
                     const float* __restrict__ b_attn,
                     char* __restrict__ dbase, int b)
{
    __shared__ __half As[128][40];   // [m][k], 8-half pad: conflict-free frags
    __shared__ __half Wt[128][40];   // [n][k] transposed W tile

    const int tid  = threadIdx.x;
    const int warp = tid >> 5, lane = tid & 31;
    const int wm = warp & 3, wn = warp >> 2;      // 4 x 2 warp grid
    const int lr = lane >> 2;                     // 0..7
    const int koff = (lane & 3) * 2;              // 0,2,4,6
    const int rowBase = blockIdx.y * 128;
    const int colBase = blockIdx.x * 128;
    const float* A = x + (size_t)b * SEQ * D_MODEL;

    float acc[2][8][4];
#pragma unroll
    for (int mt = 0; mt < 2; mt++)
#pragma unroll
        for (int nt = 0; nt < 8; nt++)
#pragma unroll
            for (int j = 0; j < 4; j++) acc[mt][nt][j] = 0.f;

    for (int k0 = 0; k0 < D_MODEL; k0 += 32) {
        __syncthreads();
        // A tile: 128x32 fp32 = 1024 float4, 4 per thread -> fp16 [m][k]
#pragma unroll
        for (int i = 0; i < 4; i++) {
            int idx = tid + i * 256;
            int r = idx >> 3, c4 = (idx & 7) << 2;
            float4 v = *(const float4*)&A[(size_t)(rowBase + r) * D_MODEL + k0 + c4];
            unsigned lo = packh2(v.x, v.y), hi = packh2(v.z, v.w);
            *(uint32_t*)&As[r][c4]     = lo;
            *(uint32_t*)&As[r][c4 + 2] = hi;
        }
        // W tile: 32x128 fp32 = 1024 float4, 4 per thread -> fp16 transposed [n][k]
#pragma unroll
        for (int i = 0; i < 4; i++) {
            int idx = tid + i * 256;
            int kr = idx >> 5, n4 = (idx & 31) << 2;
            float4 v = *(const float4*)&W_attn[(size_t)(k0 + kr) * 2304 + colBase + n4];
            Wt[n4 + 0][kr] = __float2half_rn(v.x);
            Wt[n4 + 1][kr] = __float2half_rn(v.y);
            Wt[n4 + 2][kr] = __float2half_rn(v.z);
            Wt[n4 + 3][kr] = __float2half_rn(v.w);
        }
        __syncthreads();

#pragma unroll
        for (int kc = 0; kc < 32; kc += 16) {
            uint32_t qa[2][4];
#pragma unroll
            for (int mt = 0; mt < 2; mt++) {
                int r = wm * 32 + mt * 16 + lr;
                qa[mt][0] = *(const uint32_t*)&As[r][kc + koff];
                qa[mt][1] = *(const uint32_t*)&As[r + 8][kc + koff];
                qa[mt][2] = *(const uint32_t*)&As[r][kc + koff + 8];
                qa[mt][3] = *(const uint32_t*)&As[r + 8][kc + koff + 8];
            }
#pragma unroll
            for (int nt = 0; nt < 8; nt++) {
                int n = wn * 64 + nt * 8 + lr;
                uint32_t wb[2];
                wb[0] = *(const uint32_t*)&Wt[n][kc + koff];
                wb[1] = *(const uint32_t*)&Wt[n][kc + koff + 8];
                mma16816(acc[0][nt], qa[0], wb);
                mma16816(acc[1][nt], qa[1], wb);
            }
        }
    }

    // Epilogue: scatter fp16. Thread owns cols gcol,gcol+1 per nt; rows r0,r0+8 per mt.
#pragma unroll
    for (int nt = 0; nt < 8; nt++) {
        int gcol = colBase + wn * 64 + nt * 8 + (lane & 3) * 2;
        int which = gcol / 768;                 // 0=Q 1=K 2=V
        int cc = gcol - which * 768;
        int h = cc >> 6, d0 = cc & 63;
        float b0 = b_attn[gcol], b1 = b_attn[gcol + 1];
        float sc = (which == 0) ? QSCALE : 1.f;
#pragma unroll
        for (int mt = 0; mt < 2; mt++) {
#pragma unroll
            for (int rh = 0; rh < 2; rh++) {
                int t = rowBase + wm * 32 + mt * 16 + lr + rh * 8;
                float v0 = (acc[mt][nt][rh * 2 + 0] + b0) * sc;
                float v1 = (acc[mt][nt][rh * 2 + 1] + b1) * sc;
                char* pa;
                if (which == 0) {
                    pa = dbase + (size_t)(b * SEQ + t) * 3072 + (size_t)(h * 64 + d0) * 2;
                } else {
                    int c = h * SEQ + t;
                    int p = c / 6, s = c - p * 6;
                    pa = dbase + (size_t)p * 3072 + 1536 + s * 256
                       + (which == 2 ? 128 : 0) + d0 * 2;
                }
                *(uint32_t*)pa = packh2(v0, v1);
            }
        }
    }
}

// ---------------------------------------------------------------------------
// Kernel 2 — tensor-core flash attention for one batch (unchanged from R8).
// ---------------------------------------------------------------------------
__global__ __launch_bounds__(128)
void attn_mma_kernel(const int* __restrict__ attn_mask,
                     char* __restrict__ dbase, int b)
{
    const int qt   = (int)gridDim.x - 1 - (int)blockIdx.x;  // heavy tiles first
    const int h    = blockIdx.y;
    const int tid  = threadIdx.x;
    const int warp = tid >> 5, lane = tid & 31;
    const int lr   = lane >> 2;          // 0..7
    const int koff = (lane & 3) * 2;     // 0,2,4,6

    __shared__ __half Qs[64][72];
    __shared__ __half Ks[64][72];
    __shared__ __half Vt[64][72];        // [dim][swizzled key]
    __shared__ int    msk[64];

#pragma unroll
    for (int i = 0; i < 4; i++) {
        int idx = tid + i * 128;
        int rr = idx >> 3, c8 = (idx & 7) * 8;
        const char* src = dbase + (size_t)(b * SEQ + qt * 64 + rr) * 3072
                        + (size_t)(h * 64 + c8) * 2;
        *(uint4*)&Qs[rr][c8] = *(const uint4*)src;
    }
    __syncthreads();

    uint32_t qa[4][4];
    const int qr = warp * 16 + lr;
#pragma unroll
    for (int ks = 0; ks < 4; ks++) {
        qa[ks][0] = *(const uint32_t*)&Qs[qr][ks * 16 + koff];
        qa[ks][1] = *(const uint32_t*)&Qs[qr + 8][ks * 16 + koff];
        qa[ks][2] = *(const uint32_t*)&Qs[qr][ks * 16 + koff + 8];
        qa[ks][3] = *(const uint32_t*)&Qs[qr + 8][ks * 16 + koff + 8];
    }

    const int q0 = qt * 64 + qr;
    const int q1 = q0 + 8;

    float m0 = -1e30f, m1 = -1e30f, l0 = 0.f, l1 = 0.f;
    float O[8][4];
#pragma unroll
    for (int nb = 0; nb < 8; nb++)
#pragma unroll
        for (int j = 0; j < 4; j++) O[nb][j] = 0.f;

    for (int kt = 0; kt <= qt; kt++) {
        __syncthreads();
#pragma unroll
        for (int i = 0; i < 4; i++) {
            int idx = tid + i * 128;
            int rr = idx >> 3, c8 = (idx & 7) * 8;
            int c = h * SEQ + kt * 64 + rr;
            int p = c / 6, s = c - p * 6;
            const char* base = dbase + (size_t)p * 3072 + 1536 + s * 256;
            *(uint4*)&Ks[rr][c8] = *(const uint4*)(base + c8 * 2);
            uint4 vv = *(const uint4*)(base + 128 + c8 * 2);
            int vcol = (rr + c8) & 63;
            Vt[c8 + 0][vcol] = __ushort_as_half((unsigned short)(vv.x & 0xFFFFu));
            Vt[c8 + 1][vcol] = __ushort_as_half((unsigned short)(vv.x >> 16));
            Vt[c8 + 2][vcol] = __ushort_as_half((unsigned short)(vv.y & 0xFFFFu));
            Vt[c8 + 3][vcol] = __ushort_as_half((unsigned short)(vv.y >> 16));
            Vt[c8 + 4][vcol] = __ushort_as_half((unsigned short)(vv.z & 0xFFFFu));
            Vt[c8 + 5][vcol] = __ushort_as_half((unsigned short)(vv.z >> 16));
            Vt[c8 + 6][vcol] = __ushort_as_half((unsigned short)(vv.w & 0xFFFFu));
            Vt[c8 + 7][vcol] = __ushort_as_half((unsigned short)(vv.w >> 16));
        }
        if (tid < 64) msk[tid] = attn_mask[b * SEQ + kt * 64 + tid];
        __syncthreads();

        float S[8][4];
#pragma unroll
        for (int nb = 0; nb < 8; nb++)
#pragma unroll
            for (int j = 0; j < 4; j++) S[nb][j] = 0.f;
#pragma unroll
        for (int ks = 0; ks < 4; ks++) {
#pragma unroll
            for (int nb = 0; nb < 8; nb++) {
                uint32_t kb[2];
                kb[0] = *(const uint32_t*)&Ks[nb * 8 + lr][ks * 16 + koff];
                kb[1] = *(const uint32_t*)&Ks[nb * 8 + lr][ks * 16 + koff + 8];
                mma16816(S[nb], qa[ks], kb);
            }
        }

        const bool diag = (kt == qt);
        float mx0 = -1e30f, mx1 = -1e30f;
#pragma unroll
        for (int nb = 0; nb < 8; nb++) {
            int cc = nb * 8 + koff;
            int kj = kt * 64 + cc;
            bool ok0 = msk[cc] != 0, ok1 = msk[cc + 1] != 0;
            bool a00 = ok0 && (!diag || kj     <= q0);
            bool a01 = ok1 && (!diag || kj + 1 <= q0);
            bool a10 = ok0 && (!diag || kj     <= q1);
            bool a11 = ok1 && (!diag || kj + 1 <= q1);
            S[nb][0] = a00 ? S[nb][0] : -1e30f;
            S[nb][1] = a01 ? S[nb][1] : -1e30f;
            S[nb][2] = a10 ? S[nb][2] : -1e30f;
            S[nb][3] = a11 ? S[nb][3] : -1e30f;
            mx0 = fmaxf(mx0, fmaxf(S[nb][0], S[nb][1]));
            mx1 = fmaxf(mx1, fmaxf(S[nb][2], S[nb][3]));
        }
        mx0 = fmaxf(mx0, __shfl_xor_sync(0xffffffffu, mx0, 1));
        mx0 = fmaxf(mx0, __shfl_xor_sync(0xffffffffu, mx0, 2));
        mx1 = fmaxf(mx1, __shfl_xor_sync(0xffffffffu, mx1, 1));
        mx1 = fmaxf(mx1, __shfl_xor_sync(0xffffffffu, mx1, 2));
        float m0n = fmaxf(m0, mx0), m1n = fmaxf(m1, mx1);
        float corr0 = ex2(m0 - m0n), corr1 = ex2(m1 - m1n);
        m0 = m0n; m1 = m1n;

        uint32_t pa[4][4];
        float sum0 = 0.f, sum1 = 0.f;
#pragma unroll
        for (int nb = 0; nb < 8; nb++) {
            float p00 = ex2(S[nb][0] - m0), p01 = ex2(S[nb][1] - m0);
            float p10 = ex2(S[nb][2] - m1), p11 = ex2(S[nb][3] - m1);
            sum0 += p00 + p01; sum1 += p10 + p11;
            int ksv = nb >> 1, hi = (nb & 1) * 2;
            pa[ksv][hi + 0] = packh2(p00, p01);
            pa[ksv][hi + 1] = packh2(p10, p11);
        }
        l0 = l0 * corr0 + sum0;
        l1 = l1 * corr1 + sum1;
#pragma unroll
        for (int nb = 0; nb < 8; nb++) {
            O[nb][0] *= corr0; O[nb][1] *= corr0;
            O[nb][2] *= corr1; O[nb][3] *= corr1;
        }

#pragma unroll
        for (int ksv = 0; ksv < 4; ksv++) {
#pragma unroll
            for (int nb = 0; nb < 8; nb++) {
                uint32_t vb[2];
                int k0c = ksv * 16 + koff;
                vb[0] = *(const uint32_t*)&Vt[nb * 8 + lr][(k0c + 8 * nb) & 63];
                vb[1] = *(const uint32_t*)&Vt[nb * 8 + lr][(k0c + 8 + 8 * nb) & 63];
                mma16816(O[nb], pa[ksv], vb);
            }
        }
    }

    l0 += __shfl_xor_sync(0xffffffffu, l0, 1);
    l0 += __shfl_xor_sync(0xffffffffu, l0, 2);
    l1 += __shfl_xor_sync(0xffffffffu, l1, 1);
    l1 += __shfl_xor_sync(0xffffffffu, l1, 2);
    float inv0 = 1.f / l0, inv1 = 1.f / l1;

    char* r0p = dbase + (size_t)(b * SEQ + q0) * 3072 + (size_t)(h * 64 + koff) * 2;
    char* r1p = dbase + (size_t)(b * SEQ + q1) * 3072 + (size_t)(h * 64 + koff) * 2;
#pragma unroll
    for (int nb = 0; nb < 8; nb++) {
        *(uint32_t*)(r0p + nb * 16) = packh2(O[nb][0] * inv0, O[nb][1] * inv0);
        *(uint32_t*)(r1p + nb * 16) = packh2(O[nb][2] * inv1, O[nb][3] * inv1);
    }
}

// ---------------------------------------------------------------------------
// Kernel 3 — proj GEMM (unchanged from R8): out = ATT(fp16 in-place) @ W_proj + b.
// BM=32, BN=768 (block owns full row stripe -> in-place overwrite safe), BK=8.
// ---------------------------------------------------------------------------
__global__ __launch_bounds__(256)
void proj_kernel(const char* __restrict__ att_base,
                 const float* __restrict__ W_proj,
                 const float* __restrict__ b_proj,
                 float* __restrict__ out)
{
    __shared__ float As[32][8];
    __shared__ float Bs[8][768];

    const int tid = threadIdx.x;
    const int r = tid >> 3, g = tid & 7;
    const int rowBase = blockIdx.x * 32;

    float4 acc[24];
#pragma unroll
    for (int j = 0; j < 24; j++) acc[j] = make_float4(0.f, 0.f, 0.f, 0.f);

    for (int k0 = 0; k0 < D_MODEL; k0 += 8) {
        __syncthreads();
        if (tid < 32) {
            uint4 u = *(const uint4*)(att_base + (size_t)(rowBase + tid) * 3072
                                      + (size_t)k0 * 2);
            float2 f0 = unpack2(u.x), f1 = unpack2(u.y);
            float2 f2 = unpack2(u.z), f3 = unpack2(u.w);
            As[tid][0] = f0.x; As[tid][1] = f0.y; As[tid][2] = f1.x; As[tid][3] = f1.y;
            As[tid][4] = f2.x; As[tid][5] = f2.y; As[tid][6] = f3.x; As[tid][7] = f3.y;
        }
#pragma unroll
        for (int i = 0; i < 6; i++) {
            int idx = tid + i * 256;
            int kb = idx / 192, c4 = (idx - kb * 192) << 2;
            float4 v = *(const float4*)&W_proj[(size_t)(k0 + kb) * D_MODEL + c4];
            Bs[kb][c4] = v.x; Bs[kb][c4 + 1] = v.y;
            Bs[kb][c4 + 2] = v.z; Bs[kb][c4 + 3] = v.w;
        }
        __syncthreads();
#pragma unroll
        for (int k = 0; k < 8; k++) {
            float a = As[r][k];
#pragma unroll
            for (int j = 0; j < 24; j++) {
                float4 bb = *(const float4*)&Bs[k][g * 4 + j * 32];
                acc[j].x += a * bb.x; acc[j].y += a * bb.y;
                acc[j].z += a * bb.z; acc[j].w += a * bb.w;
            }
        }
    }
    __syncthreads();
#pragma unroll
    for (int j = 0; j < 24; j++) {
        int cofs = g * 4 + j * 32;
        float4 bv = *(const float4*)&b_proj[cofs];
        float4 o;
        o.x = acc[j].x + bv.x; o.y = acc[j].y + bv.y;
        o.z = acc[j].z + bv.z; o.w = acc[j].w + bv.w;
        *(float4*)&out[(size_t)(rowBase + r) * D_MODEL + cofs] = o;
    }
}

// ---------------------------------------------------------------------------
extern "C" void kernel_launch(void* const* d_in, const int* in_sizes, int n_in,
                              void* d_out, int out_size)
{
    const float* x      = (const float*)d_in[0];
    const int*   amask  = (const int*)d_in[1];
    const float* W_attn = (const float*)d_in[2];
    const float* b_attn = (const float*)d_in[3];
    const float* W_proj = (const float*)d_in[4];
    const float* b_proj = (const float*)d_in[5];
    float*       out    = (float*)d_out;
    char*        dbase  = (char*)d_out;

    for (int b = 0; b < BATCH; b++) {
        qkv_hmma_kernel<<<dim3(2304 / 128, SEQ / 128), 256>>>(x, W_attn, b_attn, dbase, b);
        attn_mma_kernel<<<dim3(SEQ / 64, N_HEADS), 128>>>(amask, dbase, b);
    }
    proj_kernel<<<M_TOT / 32, 256>>>(dbase, W_proj, b_proj, out);
}

// round 10
// speedup vs baseline: 7.4051x; 1.5054x over previous
#include <cuda_runtime.h>
#include <cuda_fp16.h>
#include <cstdint>

#define D_MODEL 768
#define N_HEADS 12
#define BATCH 2
#define SEQ 4096
#define M_TOT 8192
// 1/sqrt(64) * log2(e) folded into Q at GEMM time (softmax done in base-2)
#define QSCALE 0.1803368801f

// ---------------------------------------------------------------------------
// Scratch lives inside d_out (24 MiB), 8192 regions x 3072 B:
//   [ +0,    +1536) : Q fp16 (written by qkv gemm) then ATT fp16 (overwritten
//                     in-place by attn for its own rows/head slice only)
//   [ +1536, +3072) : striped K/V pool (one batch), chunk c = h*4096+t:
//                     addr = (c/6)*3072 + 1536 + (c%6)*256  (K 128B | V 128B)
// ---------------------------------------------------------------------------

__device__ __forceinline__ unsigned packh2(float a, float b) {
    unsigned lo = (unsigned)__half_as_ushort(__float2half_rn(a));
    unsigned hi = (unsigned)__half_as_ushort(__float2half_rn(b));
    return lo | (hi << 16);
}
__device__ __forceinline__ float ex2(float x) {
    float y; asm("ex2.approx.f32 %0, %1;" : "=f"(y) : "f"(x)); return y;
}
__device__ __forceinline__ void mma16816(float* d, const uint32_t* a,
                                         const uint32_t* b) {
    asm volatile(
        "mma.sync.aligned.m16n8k16.row.col.f32.f16.f16.f32 "
        "{%0,%1,%2,%3}, {%4,%5,%6,%7}, {%8,%9}, {%0,%1,%2,%3};"
        : "+f"(d[0]), "+f"(d[1]), "+f"(d[2]), "+f"(d[3])
        : "r"(a[0]), "r"(a[1]), "r"(a[2]), "r"(a[3]), "r"(b[0]), "r"(b[1]));
}

// ---------------------------------------------------------------------------
// Kernel 1 — HMMA QKV GEMM, double-buffered pipeline.
// BM=128, BN=128, BK=32, 256 thr = 8 warps (4m x 2n), warp tile 32x64.
// ---------------------------------------------------------------------------
__global__ __launch_bounds__(256)
void qkv_hmma_kernel(const float* __restrict__ x,
                     const float* __restrict__ W_attn,
                     const float* __restrict__ b_attn,
                     char* __restrict__ dbase, int b)
{
    __shared__ __half As[2][128][40];   // [buf][m][k]
    __shared__ __half Wt[2][128][40];   // [buf][n][k] (transposed W)

    const int tid  = threadIdx.x;
    const int warp = tid >> 5, lane = tid & 31;
    const int wm = warp & 3, wn = warp >> 2;
    const int lr = lane >> 2;
    const int koff = (lane & 3) * 2;
    const int rowBase = blockIdx.y * 128;
    const int colBase = blockIdx.x * 128;
    const float* A = x + (size_t)b * SEQ * D_MODEL;

    float acc[2][8][4];
#pragma unroll
    for (int mt = 0; mt < 2; mt++)
#pragma unroll
        for (int nt = 0; nt < 8; nt++)
#pragma unroll
            for (int j = 0; j < 4; j++) acc[mt][nt][j] = 0.f;

    float4 a_pre[4], w_pre[4];

#define QKV_LDG(IT) do {                                                        \
    int k0_ = (IT) * 32;                                                        \
    _Pragma("unroll")                                                           \
    for (int i = 0; i < 4; i++) {                                               \
        int idx = tid + i * 256;                                                \
        int r = idx >> 3, c4 = (idx & 7) << 2;                                  \
        a_pre[i] = *(const float4*)&A[(size_t)(rowBase + r) * D_MODEL + k0_ + c4]; \
    }                                                                           \
    _Pragma("unroll")                                                           \
    for (int i = 0; i < 4; i++) {                                               \
        int idx = tid + i * 256;                                                \
        int kr = idx >> 5, n4 = (idx & 31) << 2;                                \
        w_pre[i] = *(const float4*)&W_attn[(size_t)(k0_ + kr) * 2304 + colBase + n4]; \
    }                                                                           \
} while (0)

#define QKV_STS(BUF) do {                                                       \
    _Pragma("unroll")                                                           \
    for (int i = 0; i < 4; i++) {                                               \
        int idx = tid + i * 256;                                                \
        int r = idx >> 3, c4 = (idx & 7) << 2;                                  \
        *(uint32_t*)&As[BUF][r][c4]     = packh2(a_pre[i].x, a_pre[i].y);       \
        *(uint32_t*)&As[BUF][r][c4 + 2] = packh2(a_pre[i].z, a_pre[i].w);       \
        int kr = idx >> 5, n4 = (idx & 31) << 2;                                \
        Wt[BUF][n4 + 0][kr] = __float2half_rn(w_pre[i].x);                      \
        Wt[BUF][n4 + 1][kr] = __float2half_rn(w_pre[i].y);                      \
        Wt[BUF][n4 + 2][kr] = __float2half_rn(w_pre[i].z);                      \
        Wt[BUF][n4 + 3][kr] = __float2half_rn(w_pre[i].w);                      \
    }                                                                           \
} while (0)

    QKV_LDG(0);
    QKV_STS(0);
    __syncthreads();

    for (int it = 0; it < 24; ++it) {
        const int cur = it & 1;
        const bool more = (it + 1 < 24);
        if (more) QKV_LDG(it + 1);

#pragma unroll
        for (int kc = 0; kc < 32; kc += 16) {
            uint32_t qa[2][4];
#pragma unroll
            for (int mt = 0; mt < 2; mt++) {
                int r = wm * 32 + mt * 16 + lr;
                qa[mt][0] = *(const uint32_t*)&As[cur][r][kc + koff];
                qa[mt][1] = *(const uint32_t*)&As[cur][r + 8][kc + koff];
                qa[mt][2] = *(const uint32_t*)&As[cur][r][kc + koff + 8];
                qa[mt][3] = *(const uint32_t*)&As[cur][r + 8][kc + koff + 8];
            }
#pragma unroll
            for (int nt = 0; nt < 8; nt++) {
                int n = wn * 64 + nt * 8 + lr;
                uint32_t wb[2];
                wb[0] = *(const uint32_t*)&Wt[cur][n][kc + koff];
                wb[1] = *(const uint32_t*)&Wt[cur][n][kc + koff + 8];
                mma16816(acc[0][nt], qa[0], wb);
                mma16816(acc[1][nt], qa[1], wb);
            }
        }

        if (more) {
            __syncthreads();
            QKV_STS(1 - cur);
            __syncthreads();
        }
    }
#undef QKV_LDG
#undef QKV_STS

    // Epilogue: fp16 scatter (unchanged from R9)
#pragma unroll
    for (int nt = 0; nt < 8; nt++) {
        int gcol = colBase + wn * 64 + nt * 8 + (lane & 3) * 2;
        int which = gcol / 768;
        int cc = gcol - which * 768;
        int h = cc >> 6, d0 = cc & 63;
        float b0 = b_attn[gcol], b1 = b_attn[gcol + 1];
        float sc = (which == 0) ? QSCALE : 1.f;
#pragma unroll
        for (int mt = 0; mt < 2; mt++) {
#pragma unroll
            for (int rh = 0; rh < 2; rh++) {
                int t = rowBase + wm * 32 + mt * 16 + lr + rh * 8;
                float v0 = (acc[mt][nt][rh * 2 + 0] + b0) * sc;
                float v1 = (acc[mt][nt][rh * 2 + 1] + b1) * sc;
                char* pa;
                if (which == 0) {
                    pa = dbase + (size_t)(b * SEQ + t) * 3072 + (size_t)(h * 64 + d0) * 2;
                } else {
                    int c = h * SEQ + t;
                    int p = c / 6, s = c - p * 6;
                    pa = dbase + (size_t)p * 3072 + 1536 + s * 256
                       + (which == 2 ? 128 : 0) + d0 * 2;
                }
                *(uint32_t*)pa = packh2(v0, v1);
            }
        }
    }
}

// ---------------------------------------------------------------------------
// Kernel 2 — tensor-core flash attention (unchanged from R9).
// ---------------------------------------------------------------------------
__global__ __launch_bounds__(128)
void attn_mma_kernel(const int* __restrict__ attn_mask,
                     char* __restrict__ dbase, int b)
{
    const int qt   = (int)gridDim.x - 1 - (int)blockIdx.x;
    const int h    = blockIdx.y;
    const int tid  = threadIdx.x;
    const int warp = tid >> 5, lane = tid & 31;
    const int lr   = lane >> 2;
    const int koff = (lane & 3) * 2;

    __shared__ __half Qs[64][72];
    __shared__ __half Ks[64][72];
    __shared__ __half Vt[64][72];
    __shared__ int    msk[64];

#pragma unroll
    for (int i = 0; i < 4; i++) {
        int idx = tid + i * 128;
        int rr = idx >> 3, c8 = (idx & 7) * 8;
        const char* src = dbase + (size_t)(b * SEQ + qt * 64 + rr) * 3072
                        + (size_t)(h * 64 + c8) * 2;
        *(uint4*)&Qs[rr][c8] = *(const uint4*)src;
    }
    __syncthreads();

    uint32_t qa[4][4];
    const int qr = warp * 16 + lr;
#pragma unroll
    for (int ks = 0; ks < 4; ks++) {
        qa[ks][0] = *(const uint32_t*)&Qs[qr][ks * 16 + koff];
        qa[ks][1] = *(const uint32_t*)&Qs[qr + 8][ks * 16 + koff];
        qa[ks][2] = *(const uint32_t*)&Qs[qr][ks * 16 + koff + 8];
        qa[ks][3] = *(const uint32_t*)&Qs[qr + 8][ks * 16 + koff + 8];
    }

    const int q0 = qt * 64 + qr;
    const int q1 = q0 + 8;

    float m0 = -1e30f, m1 = -1e30f, l0 = 0.f, l1 = 0.f;
    float O[8][4];
#pragma unroll
    for (int nb = 0; nb < 8; nb++)
#pragma unroll
        for (int j = 0; j < 4; j++) O[nb][j] = 0.f;

    for (int kt = 0; kt <= qt; kt++) {
        __syncthreads();
#pragma unroll
        for (int i = 0; i < 4; i++) {
            int idx = tid + i * 128;
            int rr = idx >> 3, c8 = (idx & 7) * 8;
            int c = h * SEQ + kt * 64 + rr;
            int p = c / 6, s = c - p * 6;
            const char* base = dbase + (size_t)p * 3072 + 1536 + s * 256;
            *(uint4*)&Ks[rr][c8] = *(const uint4*)(base + c8 * 2);
            uint4 vv = *(const uint4*)(base + 128 + c8 * 2);
            int vcol = (rr + c8) & 63;
            Vt[c8 + 0][vcol] = __ushort_as_half((unsigned short)(vv.x & 0xFFFFu));
            Vt[c8 + 1][vcol] = __ushort_as_half((unsigned short)(vv.x >> 16));
            Vt[c8 + 2][vcol] = __ushort_as_half((unsigned short)(vv.y & 0xFFFFu));
            Vt[c8 + 3][vcol] = __ushort_as_half((unsigned short)(vv.y >> 16));
            Vt[c8 + 4][vcol] = __ushort_as_half((unsigned short)(vv.z & 0xFFFFu));
            Vt[c8 + 5][vcol] = __ushort_as_half((unsigned short)(vv.z >> 16));
            Vt[c8 + 6][vcol] = __ushort_as_half((unsigned short)(vv.w & 0xFFFFu));
            Vt[c8 + 7][vcol] = __ushort_as_half((unsigned short)(vv.w >> 16));
        }
        if (tid < 64) msk[tid] = attn_mask[b * SEQ + kt * 64 + tid];
        __syncthreads();

        float S[8][4];
#pragma unroll
        for (int nb = 0; nb < 8; nb++)
#pragma unroll
            for (int j = 0; j < 4; j++) S[nb][j] = 0.f;
#pragma unroll
        for (int ks = 0; ks < 4; ks++) {
#pragma unroll
            for (int nb = 0; nb < 8; nb++) {
                uint32_t kb[2];
                kb[0] = *(const uint32_t*)&Ks[nb * 8 + lr][ks * 16 + koff];
                kb[1] = *(const uint32_t*)&Ks[nb * 8 + lr][ks * 16 + koff + 8];
                mma16816(S[nb], qa[ks], kb);
            }
        }

        const bool diag = (kt == qt);
        float mx0 = -1e30f, mx1 = -1e30f;
#pragma unroll
        for (int nb = 0; nb < 8; nb++) {
            int cc = nb * 8 + koff;
            int kj = kt * 64 + cc;
            bool ok0 = msk[cc] != 0, ok1 = msk[cc + 1] != 0;
            bool a00 = ok0 && (!diag || kj     <= q0);
            bool a01 = ok1 && (!diag || kj + 1 <= q0);
            bool a10 = ok0 && (!diag || kj     <= q1);
            bool a11 = ok1 && (!diag || kj + 1 <= q1);
            S[nb][0] = a00 ? S[nb][0] : -1e30f;
            S[nb][1] = a01 ? S[nb][1] : -1e30f;
            S[nb][2] = a10 ? S[nb][2] : -1e30f;
            S[nb][3] = a11 ? S[nb][3] : -1e30f;
            mx0 = fmaxf(mx0, fmaxf(S[nb][0], S[nb][1]));
            mx1 = fmaxf(mx1, fmaxf(S[nb][2], S[nb][3]));
        }
        mx0 = fmaxf(mx0, __shfl_xor_sync(0xffffffffu, mx0, 1));
        mx0 = fmaxf(mx0, __shfl_xor_sync(0xffffffffu, mx0, 2));
        mx1 = fmaxf(mx1, __shfl_xor_sync(0xffffffffu, mx1, 1));
        mx1 = fmaxf(mx1, __shfl_xor_sync(0xffffffffu, mx1, 2));
        float m0n = fmaxf(m0, mx0), m1n = fmaxf(m1, mx1);
        float corr0 = ex2(m0 - m0n), corr1 = ex2(m1 - m1n);
        m0 = m0n; m1 = m1n;

        uint32_t pa[4][4];
        float sum0 = 0.f, sum1 = 0.f;
#pragma unroll
        for (int nb = 0; nb < 8; nb++) {
            float p00 = ex2(S[nb][0] - m0), p01 = ex2(S[nb][1] - m0);
            float p10 = ex2(S[nb][2] - m1), p11 = ex2(S[nb][3] - m1);
            sum0 += p00 + p01; sum1 += p10 + p11;
            int ksv = nb >> 1, hi = (nb & 1) * 2;
            pa[ksv][hi + 0] = packh2(p00, p01);
            pa[ksv][hi + 1] = packh2(p10, p11);
        }
        l0 = l0 * corr0 + sum0;
        l1 = l1 * corr1 + sum1;
#pragma unroll
        for (int nb = 0; nb < 8; nb++) {
            O[nb][0] *= corr0; O[nb][1] *= corr0;
            O[nb][2] *= corr1; O[nb][3] *= corr1;
        }

#pragma unroll
        for (int ksv = 0; ksv < 4; ksv++) {
#pragma unroll
            for (int nb = 0; nb < 8; nb++) {
                uint32_t vb[2];
                int k0c = ksv * 16 + koff;
                vb[0] = *(const uint32_t*)&Vt[nb * 8 + lr][(k0c + 8 * nb) & 63];
                vb[1] = *(const uint32_t*)&Vt[nb * 8 + lr][(k0c + 8 + 8 * nb) & 63];
                mma16816(O[nb], pa[ksv], vb);
            }
        }
    }

    l0 += __shfl_xor_sync(0xffffffffu, l0, 1);
    l0 += __shfl_xor_sync(0xffffffffu, l0, 2);
    l1 += __shfl_xor_sync(0xffffffffu, l1, 1);
    l1 += __shfl_xor_sync(0xffffffffu, l1, 2);
    float inv0 = 1.f / l0, inv1 = 1.f / l1;

    char* r0p = dbase + (size_t)(b * SEQ + q0) * 3072 + (size_t)(h * 64 + koff) * 2;
    char* r1p = dbase + (size_t)(b * SEQ + q1) * 3072 + (size_t)(h * 64 + koff) * 2;
#pragma unroll
    for (int nb = 0; nb < 8; nb++) {
        *(uint32_t*)(r0p + nb * 16) = packh2(O[nb][0] * inv0, O[nb][1] * inv0);
        *(uint32_t*)(r1p + nb * 16) = packh2(O[nb][2] * inv1, O[nb][3] * inv1);
    }
}

// ---------------------------------------------------------------------------
// Kernel 3 — HMMA proj GEMM with stripe ownership.
// BM=64 rows/block (128 blocks ~ one wave), full N=768 per block.
// Stage own ATT rows to dynamic smem ONCE (in-place safety), then 6 N-chunks
// of 128 with a double-buffered fp16 W tile. fp32 out + bias.
// Dynamic smem: ATTs 64x776 halves (99328 B) + Wt 2x128x40 (20480 B).
// ---------------------------------------------------------------------------
#define PROJ_SMEM_BYTES (64 * 776 * 2 + 2 * 128 * 40 * 2)

__global__ __launch_bounds__(256)
void proj_hmma_kernel(const char* __restrict__ att_base,
                      const float* __restrict__ W_proj,
                      const float* __restrict__ b_proj,
                      float* __restrict__ out)
{
    extern __shared__ char smem_raw[];
    __half (*ATTs)[776] = (__half(*)[776])smem_raw;
    __half (*Wt)[40]    = (__half(*)[40])(smem_raw + 64 * 776 * 2);  // [buf*128+n][k]

    const int tid  = threadIdx.x;
    const int warp = tid >> 5, lane = tid & 31;
    const int wm = warp & 3, wn = warp >> 2;      // 4 m-warps x 2 n-warps
    const int lr = lane >> 2;
    const int koff = (lane & 3) * 2;
    const int rowBase = blockIdx.x * 64;

    // Stage own 64 ATT rows (front halves of regions) once.
#pragma unroll
    for (int i = 0; i < 24; i++) {
        int idx = tid + i * 256;              // 0..6143
        int r = idx / 96, c8 = (idx - r * 96) * 8;
        *(uint4*)&ATTs[r][c8] =
            *(const uint4*)(att_base + (size_t)(rowBase + r) * 3072 + (size_t)c8 * 2);
    }

    float4 w_pre[4];

#define PROJ_LDG(IT, COLB) do {                                                 \
    int k0_ = (IT) * 32;                                                        \
    _Pragma("unroll")                                                           \
    for (int i = 0; i < 4; i++) {                                               \
        int idx = tid + i * 256;                                                \
        int kr = idx >> 5, n4 = (idx & 31) << 2;                                \
        w_pre[i] = *(const float4*)&W_proj[(size_t)(k0_ + kr) * 768 + (COLB) + n4]; \
    }                                                                           \
} while (0)

#define PROJ_STS(BUF) do {                                                      \
    _Pragma("unroll")                                                           \
    for (int i = 0; i < 4; i++) {                                               \
        int idx = tid + i * 256;                                                \
        int kr = idx >> 5, n4 = (idx & 31) << 2;                                \
        Wt[(BUF) * 128 + n4 + 0][kr] = __float2half_rn(w_pre[i].x);             \
        Wt[(BUF) * 128 + n4 + 1][kr] = __float2half_rn(w_pre[i].y);             \
        Wt[(BUF) * 128 + n4 + 2][kr] = __float2half_rn(w_pre[i].z);             \
        Wt[(BUF) * 128 + n4 + 3][kr] = __float2half_rn(w_pre[i].w);             \
    }                                                                           \
} while (0)

    for (int chunk = 0; chunk < 6; ++chunk) {
        const int colBase = chunk * 128;
        float acc[8][4];
#pragma unroll
        for (int nt = 0; nt < 8; nt++)
#pragma unroll
            for (int j = 0; j < 4; j++) acc[nt][j] = 0.f;

        __syncthreads();   // ATT staged / previous chunk's Wt reads complete
        PROJ_LDG(0, colBase);
        PROJ_STS(0);
        __syncthreads();

        for (int it = 0; it < 24; ++it) {
            const int cur = it & 1;
            const bool more = (it + 1 < 24);
            if (more) PROJ_LDG(it + 1, colBase);

#pragma unroll
            for (int kc = 0; kc < 32; kc += 16) {
                int ak = it * 32 + kc;
                uint32_t aa[4];
                int r = wm * 16 + lr;
                aa[0] = *(const uint32_t*)&ATTs[r][ak + koff];
                aa[1] = *(const uint32_t*)&ATTs[r + 8][ak + koff];
                aa[2] = *(const uint32_t*)&ATTs[r][ak + koff + 8];
                aa[3] = *(const uint32_t*)&ATTs[r + 8][ak + koff + 8];
#pragma unroll
                for (int nt = 0; nt < 8; nt++) {
                    int n = wn * 64 + nt * 8 + lr;
                    uint32_t wb[2];
                    wb[0] = *(const uint32_t*)&Wt[cur * 128 + n][kc + koff];
                    wb[1] = *(const uint32_t*)&Wt[cur * 128 + n][kc + koff + 8];
                    mma16816(acc[nt], aa, wb);
                }
            }

            if (more) {
                __syncthreads();
                PROJ_STS(1 - cur);
                __syncthreads();
            }
        }

        // Chunk epilogue: bias + fp32 stores (rows owned by this block).
#pragma unroll
        for (int nt = 0; nt < 8; nt++) {
            int gcol = colBase + wn * 64 + nt * 8 + koff;
            float b0 = b_proj[gcol], b1 = b_proj[gcol + 1];
#pragma unroll
            for (int rh = 0; rh < 2; rh++) {
                int row = rowBase + wm * 16 + lr + rh * 8;
                float2 o;
                o.x = acc[nt][rh * 2 + 0] + b0;
                o.y = acc[nt][rh * 2 + 1] + b1;
                *(float2*)&out[(size_t)row * 768 + gcol] = o;
            }
        }
    }
#undef PROJ_LDG
#undef PROJ_STS
}

// ---------------------------------------------------------------------------
extern "C" void kernel_launch(void* const* d_in, const int* in_sizes, int n_in,
                              void* d_out, int out_size)
{
    const float* x      = (const float*)d_in[0];
    const int*   amask  = (const int*)d_in[1];
    const float* W_attn = (const float*)d_in[2];
    const float* b_attn = (const float*)d_in[3];
    const float* W_proj = (const float*)d_in[4];
    const float* b_proj = (const float*)d_in[5];
    float*       out    = (float*)d_out;
    char*        dbase  = (char*)d_out;

    cudaFuncSetAttribute(proj_hmma_kernel,
                         cudaFuncAttributeMaxDynamicSharedMemorySize,
                         PROJ_SMEM_BYTES);

    for (int b = 0; b < BATCH; b++) {
        qkv_hmma_kernel<<<dim3(2304 / 128, SEQ / 128), 256>>>(x, W_attn, b_attn, dbase, b);
        attn_mma_kernel<<<dim3(SEQ / 64, N_HEADS), 128>>>(amask, dbase, b);
    }
    proj_hmma_kernel<<<M_TOT / 64, 256, PROJ_SMEM_BYTES>>>(dbase, W_proj, b_proj, out);
}